// round 7
// baseline (speedup 1.0000x reference)
#include <cuda_runtime.h>
#include <math.h>

#define NB   256
#define NC   768
#define NH   24
#define NHW  576
#define EMBD 2304
#define HM_Z  4          // z-chunks for heatmap (192 ch each)
#define HM_P  16         // partials per pixel (HM_Z * 4 groups)
#define PL_CHUNKS 6      // channel chunks for masked pooling (128 ch each)
#define KSPLIT 9
#define KB (EMBD / KSPLIT)   // 256

#define HM_GRID   444    // 3 CTAs/SM * 148 SMs (576-thread blocks)
#define POOL_GRID 1184   // 8 CTAs/SM * 148 SMs (256-thread blocks)

// ---- packed f32x2 helpers -------------------------------------------------
__device__ __forceinline__ void fma2(unsigned long long& acc,
                                     unsigned long long a, unsigned long long b) {
    asm("fma.rn.f32x2 %0, %1, %2, %0;" : "+l"(acc) : "l"(a), "l"(b));
}
__device__ __forceinline__ void add2(unsigned long long& acc, unsigned long long a) {
    asm("add.rn.f32x2 %0, %1, %0;" : "+l"(acc) : "l"(a));
}
__device__ __forceinline__ float2 unpack2(unsigned long long v) {
    float2 r;
    asm("mov.b64 {%0, %1}, %2;" : "=f"(r.x), "=f"(r.y) : "l"(v));
    return r;
}

// Scratch (allocation-free rule: __device__ globals)
__device__ float g_hmp[2][NB][HM_P][NHW];        // partial heatmaps (~19MB)
__device__ float g_mask[2][NB][2][NHW];          // [0]=max mask, [1]=min mask
__device__ float g_inv[2][NB][2];                // 1/nmax, 1/nmin
__device__ float g_emb[2][NB][EMBD];             // unnormalized embeddings
__device__ float g_ssq[2][NB][PL_CHUNKS];        // per-chunk sum-of-squares
__device__ float g_lpart[KSPLIT][NB][NB];        // GEMM K-split partials
__device__ float g_rowloss[NB];

// ---------------------------------------------------------------------------
// K1: partial heatmaps. Persistent grid-stride over 2048 work items.
// Item = (b, img, z): 576 threads; thread = (group g, float4 slot s),
// sums 48 channels of 4 pixels. 1 LDG.128 per 16B.
// ---------------------------------------------------------------------------
__global__ __launch_bounds__(NHW) void hm_kernel(const float* __restrict__ f1,
                                                 const float* __restrict__ f2) {
    const int g = threadIdx.x / 144;
    const int s = threadIdx.x % 144;
    const int TOTAL = NB * 2 * HM_Z;

    for (int v = blockIdx.x; v < TOTAL; v += gridDim.x) {
        const int b    = v % NB;
        const int rest = v / NB;
        const int img  = rest & 1;
        const int z    = rest >> 1;

        const float* fb = (img ? f2 : f1) + (size_t)b * NC * NHW
                        + (size_t)(z * 192 + g * 48) * NHW;
        const float4* __restrict__ base = (const float4*)fb + s;

        float ax = 0.f, ay = 0.f, az = 0.f, aw = 0.f;
        #pragma unroll 8
        for (int ci = 0; ci < 48; ci++) {
            float4 x = base[(size_t)ci * 144];
            ax += x.x; ay += x.y; az += x.z; aw += x.w;
        }
        ((float4*)&g_hmp[img][b][z * 4 + g][0])[s] = make_float4(ax, ay, az, aw);
    }
}

// ---------------------------------------------------------------------------
// K2: masks from heatmap. grid (NB, 2), block 576. Tiny.
// ---------------------------------------------------------------------------
__global__ __launch_bounds__(NHW) void mask_kernel() {
    const int img = blockIdx.y, b = blockIdx.x, hw = threadIdx.x;
    __shared__ float s_hm[NHW];

    float v = 0.f;
    #pragma unroll
    for (int p = 0; p < HM_P; p++) v += g_hmp[img][b][p][hw];
    s_hm[hw] = v;
    __syncthreads();

    const int h = hw / NH, w = hw % NH;
    float mx = v, mn = v;
    #pragma unroll
    for (int dh = -1; dh <= 1; dh++) {
        #pragma unroll
        for (int dw = -1; dw <= 1; dw++) {
            int hh = h + dh, ww = w + dw;
            if (hh >= 0 && hh < NH && ww >= 0 && ww < NH) {
                float nb = s_hm[hh * NH + ww];
                mx = fmaxf(mx, nb);
                mn = fminf(mn, nb);
            }
        }
    }
    const bool corner = (h == 0 || h == NH - 1) && (w == 0 || w == NH - 1);
    const bool ismax  = (v >= mx) && !corner;
    const bool ismin  = (v <= mn) && !corner;
    g_mask[img][b][0][hw] = ismax ? 1.f : 0.f;
    g_mask[img][b][1][hw] = ismin ? 1.f : 0.f;
    const int nmax = __syncthreads_count(ismax);
    const int nmin = __syncthreads_count(ismin);
    if (hw == 0) {
        g_inv[img][b][0] = 1.f / (float)nmax;
        g_inv[img][b][1] = 1.f / (float)nmin;
    }
}

// ---------------------------------------------------------------------------
// K3: masked pooling, persistent grid-stride over 3072 items, packed FMAs.
// Also emits deterministic per-chunk sum-of-squares partials (g_ssq).
// ---------------------------------------------------------------------------
__global__ __launch_bounds__(256) void pool_kernel(const float* __restrict__ f1,
                                                   const float* __restrict__ f2) {
    __shared__ __align__(16) float s_mmax[NHW];
    __shared__ __align__(16) float s_mmin[NHW];
    __shared__ float s_inv[2];
    __shared__ float s_ssq[8];

    const int warp = threadIdx.x >> 5;
    const int lane = threadIdx.x & 31;
    const float invgap = 1.f / (float)NHW;
    const int TOTAL = NB * 2 * PL_CHUNKS;

    for (int v = blockIdx.x; v < TOTAL; v += gridDim.x) {
        const int b     = v % NB;
        const int rest  = v / NB;
        const int img   = rest & 1;
        const int chunk = rest >> 1;
        const int ch0   = chunk * (NC / PL_CHUNKS);
        const float* __restrict__ fb = (img ? f2 : f1) + (size_t)b * NC * NHW;

        __syncthreads();   // protect smem from previous iteration's readers
        for (int i = threadIdx.x; i < NHW; i += 256) {
            s_mmax[i] = g_mask[img][b][0][i];
            s_mmin[i] = g_mask[img][b][1][i];
        }
        if (threadIdx.x < 2) s_inv[threadIdx.x] = g_inv[img][b][threadIdx.x];
        __syncthreads();

        const float invmax = s_inv[0];
        const float invmin = s_inv[1];
        const ulonglong2* __restrict__ m2a = (const ulonglong2*)s_mmax;
        const ulonglong2* __restrict__ m2i = (const ulonglong2*)s_mmin;
        float* __restrict__ eb = &g_emb[img][b][0];

        float ssq = 0.f;   // lane-0 accumulates over its 16 channels
        #pragma unroll 2
        for (int ci = 0; ci < 16; ci++) {
            const int c = ch0 + warp + (ci << 3);
            const ulonglong2* __restrict__ row2 = (const ulonglong2*)(fb + (size_t)c * NHW);

            unsigned long long am = 0ull, ai = 0ull, ag = 0ull;
            #pragma unroll
            for (int i = 0; i < 4; i++) {
                int idx = lane + (i << 5);
                ulonglong2 x  = row2[idx];
                ulonglong2 ma = m2a[idx];
                ulonglong2 mi = m2i[idx];
                fma2(am, x.x, ma.x); fma2(am, x.y, ma.y);
                fma2(ai, x.x, mi.x); fma2(ai, x.y, mi.y);
                add2(ag, x.x);       add2(ag, x.y);
            }
            if (lane < 16) {
                int idx = 128 + lane;
                ulonglong2 x  = row2[idx];
                ulonglong2 ma = m2a[idx];
                ulonglong2 mi = m2i[idx];
                fma2(am, x.x, ma.x); fma2(am, x.y, ma.y);
                fma2(ai, x.x, mi.x); fma2(ai, x.y, mi.y);
                add2(ag, x.x);       add2(ag, x.y);
            }
            float2 fm = unpack2(am), fi = unpack2(ai), fg = unpack2(ag);
            float smax = fm.x + fm.y, smin = fi.x + fi.y, sgap = fg.x + fg.y;
            #pragma unroll
            for (int off = 16; off > 0; off >>= 1) {
                smax += __shfl_down_sync(0xffffffffu, smax, off);
                smin += __shfl_down_sync(0xffffffffu, smin, off);
                sgap += __shfl_down_sync(0xffffffffu, sgap, off);
            }
            if (lane == 0) {
                float a = smax * invmax;
                float m = smin * invmin;
                float g = sgap * invgap;
                eb[c]          = a;
                eb[NC + c]     = m;
                eb[2 * NC + c] = g;
                ssq += a * a + m * m + g * g;
            }
        }
        if (lane == 0) s_ssq[warp] = ssq;
        __syncthreads();
        if (threadIdx.x == 0) {
            float t = 0.f;
            #pragma unroll
            for (int i = 0; i < 8; i++) t += s_ssq[i];
            g_ssq[img][b][chunk] = t;
        }
    }
}

// ---------------------------------------------------------------------------
// GEMM on unnormalized embeddings: 64x64 tile, 4x4/thread, K-split 9 (144 CTAs
// = one full wave). Transposed smem tiles; writes raw-dot partials.
// ---------------------------------------------------------------------------
__global__ __launch_bounds__(256) void gemm_kernel() {
    __shared__ __align__(16) float As[32][68];
    __shared__ __align__(16) float Bs[32][68];
    const int tx = threadIdx.x, ty = threadIdx.y;       // 16x16
    const int tid = ty * 16 + tx;
    const int bi = blockIdx.y * 64, bj = blockIdx.x * 64;
    const int kb0 = blockIdx.z * KB;

    const int lm = tid >> 2;
    const int lk = (tid & 3) * 8;

    float acc[4][4];
    #pragma unroll
    for (int i = 0; i < 4; i++)
        #pragma unroll
        for (int j = 0; j < 4; j++) acc[i][j] = 0.f;

    for (int kc = 0; kc < KB; kc += 32) {
        const int kg = kb0 + kc + lk;
        float4 a0 = *(const float4*)&g_emb[0][bi + lm][kg];
        float4 a1 = *(const float4*)&g_emb[0][bi + lm][kg + 4];
        float4 b0 = *(const float4*)&g_emb[1][bj + lm][kg];
        float4 b1 = *(const float4*)&g_emb[1][bj + lm][kg + 4];
        As[lk + 0][lm] = a0.x; As[lk + 1][lm] = a0.y; As[lk + 2][lm] = a0.z; As[lk + 3][lm] = a0.w;
        As[lk + 4][lm] = a1.x; As[lk + 5][lm] = a1.y; As[lk + 6][lm] = a1.z; As[lk + 7][lm] = a1.w;
        Bs[lk + 0][lm] = b0.x; Bs[lk + 1][lm] = b0.y; Bs[lk + 2][lm] = b0.z; Bs[lk + 3][lm] = b0.w;
        Bs[lk + 4][lm] = b1.x; Bs[lk + 5][lm] = b1.y; Bs[lk + 6][lm] = b1.z; Bs[lk + 7][lm] = b1.w;
        __syncthreads();

        #pragma unroll
        for (int k = 0; k < 32; k++) {
            float4 av = *(const float4*)&As[k][ty * 4];
            float4 bv = *(const float4*)&Bs[k][tx * 4];
            float a[4] = {av.x, av.y, av.z, av.w};
            float bb[4] = {bv.x, bv.y, bv.z, bv.w};
            #pragma unroll
            for (int i = 0; i < 4; i++)
                #pragma unroll
                for (int j = 0; j < 4; j++)
                    acc[i][j] = fmaf(a[i], bb[j], acc[i][j]);
        }
        __syncthreads();
    }

    #pragma unroll
    for (int i = 0; i < 4; i++) {
        float4 v = make_float4(acc[i][0], acc[i][1], acc[i][2], acc[i][3]);
        *(float4*)&g_lpart[blockIdx.z][bi + ty * 4 + i][bj + tx * 4] = v;
    }
}

// ---------------------------------------------------------------------------
// Fused reduce + normalize + LSE. Block r, thread t:
//   x1 = logits[r][t] = s*inv1[r]*inv2[t]*sum_z lpart[z][r][t]   (row read)
//   x2 = logits[t][r] = s*inv1[t]*inv2[r]*sum_z lpart[z][t][r]   (col read, L2)
// rowloss[r] = lse(x1 over t) + lse(x2 over t) - 2*diag.
// ---------------------------------------------------------------------------
__global__ __launch_bounds__(256) void lse_kernel(const float* __restrict__ scale_p) {
    const int r = blockIdx.x, t = threadIdx.x;
    const int warp = t >> 5, lane = t & 31;
    __shared__ float sred[8];
    __shared__ float s_diag;

    // inverse L2 norms (deterministic fixed-order 6-way sums)
    float sq1r = 0.f, sq2r = 0.f, sq1t = 0.f, sq2t = 0.f;
    #pragma unroll
    for (int c = 0; c < PL_CHUNKS; c++) {
        sq1r += g_ssq[0][r][c];
        sq2r += g_ssq[1][r][c];
        sq1t += g_ssq[0][t][c];
        sq2t += g_ssq[1][t][c];
    }
    const float inv1r = rsqrtf(sq1r), inv2r = rsqrtf(sq2r);
    const float inv1t = rsqrtf(sq1t), inv2t = rsqrtf(sq2t);
    const float s = __ldg(scale_p);

    float d1 = 0.f, d2 = 0.f;
    #pragma unroll
    for (int z = 0; z < KSPLIT; z++) {
        d1 += g_lpart[z][r][t];   // row: coalesced
        d2 += g_lpart[z][t][r];   // col: strided, L2-resident
    }
    const float x1 = s * inv1r * inv2t * d1;   // logits[r][t]
    const float x2 = s * inv1t * inv2r * d2;   // logits[t][r]

    if (t == r) s_diag = x1;

    // --- lse of x1
    float m = x1;
    #pragma unroll
    for (int off = 16; off > 0; off >>= 1) m = fmaxf(m, __shfl_xor_sync(0xffffffffu, m, off));
    if (lane == 0) sred[warp] = m;
    __syncthreads();
    float m1 = sred[0];
    #pragma unroll
    for (int i = 1; i < 8; i++) m1 = fmaxf(m1, sred[i]);
    __syncthreads();

    float e1 = expf(x1 - m1);
    #pragma unroll
    for (int off = 16; off > 0; off >>= 1) e1 += __shfl_xor_sync(0xffffffffu, e1, off);
    if (lane == 0) sred[warp] = e1;
    __syncthreads();
    float s1 = 0.f;
    #pragma unroll
    for (int i = 0; i < 8; i++) s1 += sred[i];
    __syncthreads();

    // --- lse of x2
    float n = x2;
    #pragma unroll
    for (int off = 16; off > 0; off >>= 1) n = fmaxf(n, __shfl_xor_sync(0xffffffffu, n, off));
    if (lane == 0) sred[warp] = n;
    __syncthreads();
    float m2 = sred[0];
    #pragma unroll
    for (int i = 1; i < 8; i++) m2 = fmaxf(m2, sred[i]);
    __syncthreads();

    float e2 = expf(x2 - m2);
    #pragma unroll
    for (int off = 16; off > 0; off >>= 1) e2 += __shfl_xor_sync(0xffffffffu, e2, off);
    if (lane == 0) sred[warp] = e2;
    __syncthreads();
    float s2 = 0.f;
    #pragma unroll
    for (int i = 0; i < 8; i++) s2 += sred[i];

    if (t == 0) {
        float lse1 = m1 + logf(s1);
        float lse2 = m2 + logf(s2);
        g_rowloss[r] = lse1 + lse2 - 2.f * s_diag;
    }
}

// ---------------------------------------------------------------------------
// Final scalar: mean over rows, /2 (symmetric CE), write to d_out.
// ---------------------------------------------------------------------------
__global__ __launch_bounds__(256) void final_kernel(float* __restrict__ out) {
    float v = g_rowloss[threadIdx.x];
    #pragma unroll
    for (int off = 16; off > 0; off >>= 1)
        v += __shfl_xor_sync(0xffffffffu, v, off);
    __shared__ float sred[8];
    if ((threadIdx.x & 31) == 0) sred[threadIdx.x >> 5] = v;
    __syncthreads();
    if (threadIdx.x == 0) {
        float t = 0.f;
        #pragma unroll
        for (int i = 0; i < 8; i++) t += sred[i];
        out[0] = t * (1.0f / 512.0f);
    }
}

extern "C" void kernel_launch(void* const* d_in, const int* in_sizes, int n_in,
                              void* d_out, int out_size) {
    (void)in_sizes; (void)n_in; (void)out_size;
    const float* f1    = (const float*)d_in[0];
    const float* f2    = (const float*)d_in[1];
    const float* scale = (const float*)d_in[2];

    hm_kernel   <<<HM_GRID,   NHW>>>(f1, f2);
    mask_kernel <<<dim3(NB, 2), NHW>>>();
    pool_kernel <<<POOL_GRID, 256>>>(f1, f2);
    gemm_kernel <<<dim3(4, 4, KSPLIT), dim3(16, 16)>>>();
    lse_kernel  <<<NB, 256>>>(scale);
    final_kernel<<<1, 256>>>((float*)d_out);
}